// round 9
// baseline (speedup 1.0000x reference)
#include <cuda_runtime.h>

#define N_NODES 50000
#define IN_C 128
#define HID_C 64
#define OUT_C 32
#define N_EDGES 800000
#define TOTAL_ITEMS (N_EDGES + N_NODES)
#define NEG_SLOPE 0.2f

// ---------------- device scratch (no allocations allowed) ----------------
__device__ __align__(16) float g_h[N_NODES * HID_C];      // 12.8 MB (L2-resident)
__device__ __align__(16) float g_acc[N_NODES * HID_C];    // 12.8 MB
__device__ float g_as[N_NODES];
__device__ float g_ad[N_NODES];
__device__ int   g_cnt[N_NODES];
__device__ int   g_off[N_NODES + 1];
__device__ int   g_cursor[N_NODES];
__device__ int   g_bucket[TOTAL_ITEMS];                   // 3.4 MB: src ids grouped by dst
__device__ int   g_is64;                                  // 1 if edge_index is int64 on device

// Safe edge-index load: works for int32 buffers and (little-endian) int64 buffers.
__device__ __forceinline__ int load_idx(const int* __restrict__ ei32, int pos, int is64) {
    int v = is64 ? ei32[2 * pos] : ei32[pos];   // int64: low word holds the value (0 <= v < 2^31)
    // clamp defensively: never produce a wild address (wrong => rel_err, not a trap)
    v = v < 0 ? 0 : v;
    return v >= N_NODES ? N_NODES - 1 : v;
}

// ---------------- K0: detect edge_index dtype ----------------
// If the buffer is int64, the high 32-bit word of every entry is 0 (values < 2^31).
// If int32, the odd words are real indices ~U[0,50000): P(all 256 zero) ~ 0.
__global__ void k0_detect(const int* __restrict__ ei32) {
    __shared__ int nz;
    if (threadIdx.x == 0) nz = 0;
    __syncthreads();
    if (ei32[2 * threadIdx.x + 1] != 0) atomicOr(&nz, 1);
    __syncthreads();
    if (threadIdx.x == 0) g_is64 = (nz == 0) ? 1 : 0;
}

// ---------------- K1: h = x @ W, attention dots, init degree=1 (self-loop) ----
__global__ void __launch_bounds__(256) k1_feat(const float* __restrict__ x,
                                               const float* __restrict__ W,
                                               const float* __restrict__ att_src,
                                               const float* __restrict__ att_dst) {
    __shared__ __align__(16) float Ws[IN_C * HID_C];  // 32 KB, [k][j]
    __shared__ float as_s[HID_C];
    __shared__ float ad_s[HID_C];
    int tid = threadIdx.x;
    for (int i = tid; i < IN_C * HID_C; i += 256) Ws[i] = W[i];
    if (tid < HID_C) { as_s[tid] = att_src[tid]; ad_s[tid] = att_dst[tid]; }
    __syncthreads();

    int row = blockIdx.x * 256 + tid;
    if (row >= N_NODES) return;

    float acc[HID_C];
#pragma unroll
    for (int j = 0; j < HID_C; j++) acc[j] = 0.f;

    const float4* xr = (const float4*)(x + (size_t)row * IN_C);
#pragma unroll 4
    for (int k4 = 0; k4 < IN_C / 4; k4++) {
        float4 xv = xr[k4];
        float xa[4] = {xv.x, xv.y, xv.z, xv.w};
#pragma unroll
        for (int kk = 0; kk < 4; kk++) {
            const float4* wrow = (const float4*)&Ws[(k4 * 4 + kk) * HID_C];
            float xk = xa[kk];
#pragma unroll
            for (int j4 = 0; j4 < HID_C / 4; j4++) {
                float4 wv = wrow[j4];
                acc[4 * j4 + 0] += xk * wv.x;
                acc[4 * j4 + 1] += xk * wv.y;
                acc[4 * j4 + 2] += xk * wv.z;
                acc[4 * j4 + 3] += xk * wv.w;
            }
        }
    }

    float asum = 0.f, dsum = 0.f;
    float4* hrow = (float4*)(g_h + (size_t)row * HID_C);
#pragma unroll
    for (int j4 = 0; j4 < HID_C / 4; j4++) {
        float4 hv = make_float4(acc[4 * j4], acc[4 * j4 + 1], acc[4 * j4 + 2], acc[4 * j4 + 3]);
        asum += hv.x * as_s[4 * j4 + 0] + hv.y * as_s[4 * j4 + 1]
              + hv.z * as_s[4 * j4 + 2] + hv.w * as_s[4 * j4 + 3];
        dsum += hv.x * ad_s[4 * j4 + 0] + hv.y * ad_s[4 * j4 + 1]
              + hv.z * ad_s[4 * j4 + 2] + hv.w * ad_s[4 * j4 + 3];
        hrow[j4] = hv;
    }

    g_as[row] = asum;
    g_ad[row] = dsum;
    g_cnt[row] = 1;  // self-loop pre-counted; deterministic re-init on every replay
}

// ---------------- K2: in-degree count (int atomics only) ----------------
__global__ void __launch_bounds__(256) k2_count(const int* __restrict__ ei) {
    int e = blockIdx.x * 256 + threadIdx.x;
    if (e >= N_EDGES) return;
    int is64 = g_is64;
    int d = load_idx(ei, N_EDGES + e, is64);
    atomicAdd(&g_cnt[d], 1);
}

// ---------------- K3: single-block exclusive scan -> offsets, plant self-loops --
__global__ void __launch_bounds__(1024) k3_scan() {
    __shared__ int sums[1024];
    const int C = (N_NODES + 1023) / 1024;  // 49 nodes per thread
    int t = threadIdx.x;
    int base = t * C;

    int s = 0;
    for (int i = 0; i < C; i++) {
        int idx = base + i;
        if (idx < N_NODES) s += g_cnt[idx];
    }
    sums[t] = s;
    __syncthreads();
    // inclusive Hillis-Steele scan over 1024 partials
    for (int off = 1; off < 1024; off <<= 1) {
        int add = (t >= off) ? sums[t - off] : 0;
        __syncthreads();
        sums[t] += add;
        __syncthreads();
    }
    int run = (t == 0) ? 0 : sums[t - 1];
    for (int i = 0; i < C; i++) {
        int idx = base + i;
        if (idx < N_NODES) {
            g_off[idx] = run;
            g_bucket[run] = idx;      // self-loop goes first in each segment
            g_cursor[idx] = run + 1;
            run += g_cnt[idx];
        }
    }
    if (t == 1023) g_off[N_NODES] = sums[1023];
}

// ---------------- K4: CSR fill (src ids bucketed by dst) ----------------
__global__ void __launch_bounds__(256) k4_fill(const int* __restrict__ ei) {
    int e = blockIdx.x * 256 + threadIdx.x;
    if (e >= N_EDGES) return;
    int is64 = g_is64;
    int s = load_idx(ei, e, is64);
    int d = load_idx(ei, N_EDGES + e, is64);
    int pos = atomicAdd(&g_cursor[d], 1);
    g_bucket[pos] = s;
}

// ---------------- K5: gather + shift-free softmax + aggregate ----------------
// 16 threads per destination node; each lane owns a float4 slice of HID=64.
__global__ void __launch_bounds__(256) k5_gather() {
    int gt = blockIdx.x * 256 + threadIdx.x;
    int d = gt >> 4;
    int lane = gt & 15;
    if (d >= N_NODES) return;

    float ad = g_ad[d];
    int beg = g_off[d];
    int end = g_off[d + 1];

    float4 acc = make_float4(0.f, 0.f, 0.f, 0.f);
    float sumex = 0.f;

    int s = g_bucket[beg];           // segments are never empty (self-loop)
    for (int e = beg; e < end; e++) {
        int s_next = (e + 1 < end) ? g_bucket[e + 1] : 0;  // prefetch index
        float v = g_as[s] + ad;
        v = v > 0.f ? v : NEG_SLOPE * v;   // leaky relu
        float ex = __expf(v);              // shift-free: logits bounded ~|5|; softmax shift-invariant
        sumex += ex;
        float4 hv = *(const float4*)&g_h[(size_t)s * HID_C + lane * 4];
        acc.x += ex * hv.x; acc.y += ex * hv.y;
        acc.z += ex * hv.z; acc.w += ex * hv.w;
        s = s_next;
    }

    float inv = 1.f / (sumex + 1e-16f);
    *(float4*)&g_acc[(size_t)d * HID_C + lane * 4] =
        make_float4(acc.x * inv, acc.y * inv, acc.z * inv, acc.w * inv);
}

// ---------------- K6: out = relu(acc + bias_conv) @ W_lin + b_lin ------------
__global__ void __launch_bounds__(256) k6_out(const float* __restrict__ bias_conv,
                                              const float* __restrict__ W_lin,
                                              const float* __restrict__ b_lin,
                                              float* __restrict__ out) {
    __shared__ __align__(16) float Wl[HID_C * OUT_C];  // 8 KB, [c][j]
    __shared__ float bc[HID_C];
    __shared__ float bl[OUT_C];
    int tid = threadIdx.x;
    for (int i = tid; i < HID_C * OUT_C; i += 256) Wl[i] = W_lin[i];
    if (tid < HID_C) bc[tid] = bias_conv[tid];
    if (tid < OUT_C) bl[tid] = b_lin[tid];
    __syncthreads();

    int row = blockIdx.x * 256 + tid;
    if (row >= N_NODES) return;

    float acc[OUT_C];
#pragma unroll
    for (int j = 0; j < OUT_C; j++) acc[j] = bl[j];

    const float4* ar = (const float4*)(g_acc + (size_t)row * HID_C);
#pragma unroll 4
    for (int c4 = 0; c4 < HID_C / 4; c4++) {
        float4 av = ar[c4];
        float aa[4] = {av.x, av.y, av.z, av.w};
#pragma unroll
        for (int cc = 0; cc < 4; cc++) {
            int c = c4 * 4 + cc;
            float v = aa[cc] + bc[c];
            v = v > 0.f ? v : 0.f;  // relu
            const float4* wrow = (const float4*)&Wl[c * OUT_C];
#pragma unroll
            for (int j4 = 0; j4 < OUT_C / 4; j4++) {
                float4 wv = wrow[j4];
                acc[4 * j4 + 0] += v * wv.x;
                acc[4 * j4 + 1] += v * wv.y;
                acc[4 * j4 + 2] += v * wv.z;
                acc[4 * j4 + 3] += v * wv.w;
            }
        }
    }

    float4* orow = (float4*)(out + (size_t)row * OUT_C);
#pragma unroll
    for (int j4 = 0; j4 < OUT_C / 4; j4++)
        orow[j4] = make_float4(acc[4 * j4], acc[4 * j4 + 1], acc[4 * j4 + 2], acc[4 * j4 + 3]);
}

// ---------------- launch ----------------
extern "C" void kernel_launch(void* const* d_in, const int* in_sizes, int n_in,
                              void* d_out, int out_size) {
    const float* x         = (const float*)d_in[0];
    const int*   ei        = (const int*)d_in[1];   // int32 on device (JAX x64 off); K0 verifies
    const float* W         = (const float*)d_in[2];
    const float* att_src   = (const float*)d_in[3];
    const float* att_dst   = (const float*)d_in[4];
    const float* bias_conv = (const float*)d_in[5];
    const float* W_lin     = (const float*)d_in[6];
    const float* b_lin     = (const float*)d_in[7];
    float* out             = (float*)d_out;

    (void)in_sizes; (void)n_in; (void)out_size;

    k0_detect<<<1, 256>>>(ei);
    k1_feat<<<(N_NODES + 255) / 256, 256>>>(x, W, att_src, att_dst);
    k2_count<<<(N_EDGES + 255) / 256, 256>>>(ei);
    k3_scan<<<1, 1024>>>();
    k4_fill<<<(N_EDGES + 255) / 256, 256>>>(ei);
    {
        long long threads = (long long)N_NODES * 16;
        int blocks = (int)((threads + 255) / 256);
        k5_gather<<<blocks, 256>>>();
    }
    k6_out<<<(N_NODES + 255) / 256, 256>>>(bias_conv, W_lin, b_lin, out);
}

// round 10
// speedup vs baseline: 1.7118x; 1.7118x over previous
#include <cuda_runtime.h>

#define N_NODES 50000
#define IN_C 128
#define HID_C 64
#define OUT_C 32
#define N_EDGES 800000
#define TOTAL_ITEMS (N_EDGES + N_NODES)
#define NEG_SLOPE 0.2f
#define SCAN_TILE 1024
#define NB_SCAN ((N_NODES + SCAN_TILE - 1) / SCAN_TILE)   // 49

// ---------------- device scratch (no allocations allowed) ----------------
__device__ __align__(16) float g_h[N_NODES * HID_C];      // 12.8 MB (L2-resident)
__device__ __align__(16) float g_acc[N_NODES * HID_C];    // 12.8 MB
__device__ float g_as[N_NODES];
__device__ float g_ad[N_NODES];
__device__ int   g_cnt[N_NODES];
__device__ int   g_off[N_NODES + 1];
__device__ int   g_cursor[N_NODES];
__device__ int   g_bucket[TOTAL_ITEMS];                   // 3.4 MB: src ids grouped by dst
__device__ int   g_is64;                                  // 1 if edge_index is int64 on device
__device__ int   g_blksum[NB_SCAN];
__device__ int   g_blkoff[NB_SCAN];

// Safe edge-index load: works for int32 buffers and (little-endian) int64 buffers.
__device__ __forceinline__ int load_idx(const int* __restrict__ ei32, int pos, int is64) {
    int v = is64 ? ei32[2 * pos] : ei32[pos];
    v = v < 0 ? 0 : v;
    return v >= N_NODES ? N_NODES - 1 : v;
}

// ---------------- K0: detect edge_index dtype ----------------
__global__ void k0_detect(const int* __restrict__ ei32) {
    __shared__ int nz;
    if (threadIdx.x == 0) nz = 0;
    __syncthreads();
    if (ei32[2 * threadIdx.x + 1] != 0) atomicOr(&nz, 1);
    __syncthreads();
    if (threadIdx.x == 0) g_is64 = (nz == 0) ? 1 : 0;
}

// ---------------- K1: h = x @ W, attention dots, init degree=1 (self-loop) ----
__global__ void __launch_bounds__(256) k1_feat(const float* __restrict__ x,
                                               const float* __restrict__ W,
                                               const float* __restrict__ att_src,
                                               const float* __restrict__ att_dst) {
    __shared__ __align__(16) float Ws[IN_C * HID_C];  // 32 KB, [k][j]
    __shared__ float as_s[HID_C];
    __shared__ float ad_s[HID_C];
    int tid = threadIdx.x;
    for (int i = tid; i < IN_C * HID_C; i += 256) Ws[i] = W[i];
    if (tid < HID_C) { as_s[tid] = att_src[tid]; ad_s[tid] = att_dst[tid]; }
    __syncthreads();

    int row = blockIdx.x * 256 + tid;
    if (row >= N_NODES) return;

    float acc[HID_C];
#pragma unroll
    for (int j = 0; j < HID_C; j++) acc[j] = 0.f;

    const float4* xr = (const float4*)(x + (size_t)row * IN_C);
#pragma unroll 4
    for (int k4 = 0; k4 < IN_C / 4; k4++) {
        float4 xv = xr[k4];
        float xa[4] = {xv.x, xv.y, xv.z, xv.w};
#pragma unroll
        for (int kk = 0; kk < 4; kk++) {
            const float4* wrow = (const float4*)&Ws[(k4 * 4 + kk) * HID_C];
            float xk = xa[kk];
#pragma unroll
            for (int j4 = 0; j4 < HID_C / 4; j4++) {
                float4 wv = wrow[j4];
                acc[4 * j4 + 0] += xk * wv.x;
                acc[4 * j4 + 1] += xk * wv.y;
                acc[4 * j4 + 2] += xk * wv.z;
                acc[4 * j4 + 3] += xk * wv.w;
            }
        }
    }

    float asum = 0.f, dsum = 0.f;
    float4* hrow = (float4*)(g_h + (size_t)row * HID_C);
#pragma unroll
    for (int j4 = 0; j4 < HID_C / 4; j4++) {
        float4 hv = make_float4(acc[4 * j4], acc[4 * j4 + 1], acc[4 * j4 + 2], acc[4 * j4 + 3]);
        asum += hv.x * as_s[4 * j4 + 0] + hv.y * as_s[4 * j4 + 1]
              + hv.z * as_s[4 * j4 + 2] + hv.w * as_s[4 * j4 + 3];
        dsum += hv.x * ad_s[4 * j4 + 0] + hv.y * ad_s[4 * j4 + 1]
              + hv.z * ad_s[4 * j4 + 2] + hv.w * ad_s[4 * j4 + 3];
        hrow[j4] = hv;
    }

    g_as[row] = asum;
    g_ad[row] = dsum;
    g_cnt[row] = 1;  // self-loop pre-counted; deterministic re-init on every replay
}

// ---------------- K2: in-degree count (int atomics only) ----------------
__global__ void __launch_bounds__(256) k2_count(const int* __restrict__ ei) {
    int e = blockIdx.x * 256 + threadIdx.x;
    if (e >= N_EDGES) return;
    int is64 = g_is64;
    int d = load_idx(ei, N_EDGES + e, is64);
    atomicAdd(&g_cnt[d], 1);
}

// ---------------- K3a: per-block tile sums of g_cnt ----------------
__global__ void __launch_bounds__(SCAN_TILE) k3a_blocksum() {
    __shared__ int red[SCAN_TILE];
    int t = threadIdx.x;
    int idx = blockIdx.x * SCAN_TILE + t;
    red[t] = (idx < N_NODES) ? g_cnt[idx] : 0;
    __syncthreads();
#pragma unroll
    for (int s = SCAN_TILE / 2; s > 0; s >>= 1) {
        if (t < s) red[t] += red[t + s];
        __syncthreads();
    }
    if (t == 0) g_blksum[blockIdx.x] = red[0];
}

// ---------------- K3b: scan the 49 block sums ----------------
__global__ void __launch_bounds__(64) k3b_scanblk() {
    __shared__ int v[64];
    int t = threadIdx.x;
    v[t] = (t < NB_SCAN) ? g_blksum[t] : 0;
    __syncthreads();
#pragma unroll
    for (int off = 1; off < 64; off <<= 1) {
        int add = (t >= off) ? v[t - off] : 0;
        __syncthreads();
        v[t] += add;
        __syncthreads();
    }
    if (t < NB_SCAN) g_blkoff[t] = (t == 0) ? 0 : v[t - 1];
    if (t == 63) g_off[N_NODES] = v[63];   // grand total = TOTAL_ITEMS
}

// ---------------- K3c: per-tile exclusive scan, write offsets/self-loops/cursors --
__global__ void __launch_bounds__(SCAN_TILE) k3c_emit() {
    __shared__ int v[SCAN_TILE];
    int t = threadIdx.x;
    int idx = blockIdx.x * SCAN_TILE + t;
    int c = (idx < N_NODES) ? g_cnt[idx] : 0;
    v[t] = c;
    __syncthreads();
#pragma unroll
    for (int off = 1; off < SCAN_TILE; off <<= 1) {
        int add = (t >= off) ? v[t - off] : 0;
        __syncthreads();
        v[t] += add;
        __syncthreads();
    }
    if (idx < N_NODES) {
        int o = g_blkoff[blockIdx.x] + v[t] - c;  // exclusive
        g_off[idx] = o;
        g_bucket[o] = idx;       // self-loop first in each segment
        g_cursor[idx] = o + 1;
    }
}

// ---------------- K4: CSR fill (src ids bucketed by dst) ----------------
__global__ void __launch_bounds__(256) k4_fill(const int* __restrict__ ei) {
    int e = blockIdx.x * 256 + threadIdx.x;
    if (e >= N_EDGES) return;
    int is64 = g_is64;
    int s = load_idx(ei, e, is64);
    int d = load_idx(ei, N_EDGES + e, is64);
    int pos = atomicAdd(&g_cursor[d], 1);
    g_bucket[pos] = s;
}

// ---------------- K5: gather + shift-free softmax + aggregate ----------------
// 16 threads per destination node; each lane owns a float4 slice of HID=64.
__global__ void __launch_bounds__(256) k5_gather() {
    int gt = blockIdx.x * 256 + threadIdx.x;
    int d = gt >> 4;
    int lane = gt & 15;
    if (d >= N_NODES) return;

    float ad = g_ad[d];
    int beg = g_off[d];
    int end = g_off[d + 1];

    float4 acc = make_float4(0.f, 0.f, 0.f, 0.f);
    float sumex = 0.f;

    int s = g_bucket[beg];           // segments are never empty (self-loop)
    for (int e = beg; e < end; e++) {
        int s_next = (e + 1 < end) ? g_bucket[e + 1] : 0;  // prefetch index
        float v = g_as[s] + ad;
        v = v > 0.f ? v : NEG_SLOPE * v;   // leaky relu
        float ex = __expf(v);              // shift-free: logits bounded ~|5|; softmax shift-invariant
        sumex += ex;
        float4 hv = *(const float4*)&g_h[(size_t)s * HID_C + lane * 4];
        acc.x += ex * hv.x; acc.y += ex * hv.y;
        acc.z += ex * hv.z; acc.w += ex * hv.w;
        s = s_next;
    }

    float inv = 1.f / (sumex + 1e-16f);
    *(float4*)&g_acc[(size_t)d * HID_C + lane * 4] =
        make_float4(acc.x * inv, acc.y * inv, acc.z * inv, acc.w * inv);
}

// ---------------- K6: out = relu(acc + bias_conv) @ W_lin + b_lin ------------
__global__ void __launch_bounds__(256) k6_out(const float* __restrict__ bias_conv,
                                              const float* __restrict__ W_lin,
                                              const float* __restrict__ b_lin,
                                              float* __restrict__ out) {
    __shared__ __align__(16) float Wl[HID_C * OUT_C];  // 8 KB, [c][j]
    __shared__ float bc[HID_C];
    __shared__ float bl[OUT_C];
    int tid = threadIdx.x;
    for (int i = tid; i < HID_C * OUT_C; i += 256) Wl[i] = W_lin[i];
    if (tid < HID_C) bc[tid] = bias_conv[tid];
    if (tid < OUT_C) bl[tid] = b_lin[tid];
    __syncthreads();

    int row = blockIdx.x * 256 + tid;
    if (row >= N_NODES) return;

    float acc[OUT_C];
#pragma unroll
    for (int j = 0; j < OUT_C; j++) acc[j] = bl[j];

    const float4* ar = (const float4*)(g_acc + (size_t)row * HID_C);
#pragma unroll 4
    for (int c4 = 0; c4 < HID_C / 4; c4++) {
        float4 av = ar[c4];
        float aa[4] = {av.x, av.y, av.z, av.w};
#pragma unroll
        for (int cc = 0; cc < 4; cc++) {
            int c = c4 * 4 + cc;
            float v = aa[cc] + bc[c];
            v = v > 0.f ? v : 0.f;  // relu
            const float4* wrow = (const float4*)&Wl[c * OUT_C];
#pragma unroll
            for (int j4 = 0; j4 < OUT_C / 4; j4++) {
                float4 wv = wrow[j4];
                acc[4 * j4 + 0] += v * wv.x;
                acc[4 * j4 + 1] += v * wv.y;
                acc[4 * j4 + 2] += v * wv.z;
                acc[4 * j4 + 3] += v * wv.w;
            }
        }
    }

    float4* orow = (float4*)(out + (size_t)row * OUT_C);
#pragma unroll
    for (int j4 = 0; j4 < OUT_C / 4; j4++)
        orow[j4] = make_float4(acc[4 * j4], acc[4 * j4 + 1], acc[4 * j4 + 2], acc[4 * j4 + 3]);
}

// ---------------- launch ----------------
extern "C" void kernel_launch(void* const* d_in, const int* in_sizes, int n_in,
                              void* d_out, int out_size) {
    const float* x         = (const float*)d_in[0];
    const int*   ei        = (const int*)d_in[1];
    const float* W         = (const float*)d_in[2];
    const float* att_src   = (const float*)d_in[3];
    const float* att_dst   = (const float*)d_in[4];
    const float* bias_conv = (const float*)d_in[5];
    const float* W_lin     = (const float*)d_in[6];
    const float* b_lin     = (const float*)d_in[7];
    float* out             = (float*)d_out;

    (void)in_sizes; (void)n_in; (void)out_size;

    k0_detect<<<1, 256>>>(ei);
    k1_feat<<<(N_NODES + 255) / 256, 256>>>(x, W, att_src, att_dst);
    k2_count<<<(N_EDGES + 255) / 256, 256>>>(ei);
    k3a_blocksum<<<NB_SCAN, SCAN_TILE>>>();
    k3b_scanblk<<<1, 64>>>();
    k3c_emit<<<NB_SCAN, SCAN_TILE>>>();
    k4_fill<<<(N_EDGES + 255) / 256, 256>>>(ei);
    {
        long long threads = (long long)N_NODES * 16;
        int blocks = (int)((threads + 255) / 256);
        k5_gather<<<blocks, 256>>>();
    }
    k6_out<<<(N_NODES + 255) / 256, 256>>>(bias_conv, W_lin, b_lin, out);
}

// round 11
// speedup vs baseline: 1.9140x; 1.1181x over previous
#include <cuda_runtime.h>

#define N_NODES 50000
#define IN_C 128
#define HID_C 64
#define OUT_C 32
#define N_EDGES 800000
#define TOTAL_ITEMS (N_EDGES + N_NODES)
#define NEG_SLOPE 0.2f
#define SCAN_TILE 1024
#define NB_SCAN ((N_NODES + SCAN_TILE - 1) / SCAN_TILE)   // 49

// ---------------- device scratch (no allocations allowed) ----------------
__device__ __align__(16) float g_h[N_NODES * HID_C];      // 12.8 MB (L2-resident)
__device__ __align__(16) float g_acc[N_NODES * HID_C];    // 12.8 MB
__device__ float g_as[N_NODES];
__device__ float g_ad[N_NODES];
__device__ int   g_cnt[N_NODES];
__device__ int   g_off[N_NODES + 1];
__device__ int   g_cursor[N_NODES];
__device__ int   g_bucket[TOTAL_ITEMS];                   // 3.4 MB: src ids grouped by dst
__device__ int   g_is64;
__device__ int   g_blksum[NB_SCAN];
__device__ int   g_blkoff[NB_SCAN];

__device__ __forceinline__ int load_idx(const int* __restrict__ ei32, int pos, int is64) {
    int v = is64 ? ei32[2 * pos] : ei32[pos];
    v = v < 0 ? 0 : v;
    return v >= N_NODES ? N_NODES - 1 : v;
}

// ---------------- K0: detect edge_index dtype ----------------
__global__ void k0_detect(const int* __restrict__ ei32) {
    __shared__ int nz;
    if (threadIdx.x == 0) nz = 0;
    __syncthreads();
    if (ei32[2 * threadIdx.x + 1] != 0) atomicOr(&nz, 1);
    __syncthreads();
    if (threadIdx.x == 0) g_is64 = (nz == 0) ? 1 : 0;
}

// ---------------- K1 v2: register-tiled  h = x @ W  (4 rows x 16 cols / thread) --
// 256 threads: jq = tid&3 (16-col slice), rslot = tid>>2 (4-row group) -> 256 rows/block.
__global__ void __launch_bounds__(256) k1_feat(const float* __restrict__ x,
                                               const float* __restrict__ W,
                                               const float* __restrict__ att_src,
                                               const float* __restrict__ att_dst) {
    __shared__ __align__(16) float Ws[IN_C * HID_C];  // 32 KB, [k][j]
    __shared__ float as_s[HID_C];
    __shared__ float ad_s[HID_C];
    int tid = threadIdx.x;
    for (int i = tid; i < IN_C * HID_C; i += 256) Ws[i] = W[i];
    if (tid < HID_C) { as_s[tid] = att_src[tid]; ad_s[tid] = att_dst[tid]; }
    __syncthreads();

    const int jq = tid & 3;
    const int rslot = tid >> 2;
    const int jbase = jq * 16;
    const int row0 = blockIdx.x * 256 + rslot * 4;

    float acc[4][16];
#pragma unroll
    for (int r = 0; r < 4; r++)
#pragma unroll
        for (int j = 0; j < 16; j++) acc[r][j] = 0.f;

    const float4 z4 = make_float4(0.f, 0.f, 0.f, 0.f);
    for (int k4 = 0; k4 < IN_C / 4; k4++) {
        float4 xv[4];
#pragma unroll
        for (int r = 0; r < 4; r++) {
            int row = row0 + r;
            xv[r] = (row < N_NODES) ? *(const float4*)(x + (size_t)row * IN_C + k4 * 4) : z4;
        }
#pragma unroll
        for (int kk = 0; kk < 4; kk++) {
            const float4* wrow = (const float4*)&Ws[(k4 * 4 + kk) * HID_C + jbase];
            float4 w0 = wrow[0], w1 = wrow[1], w2 = wrow[2], w3 = wrow[3];
            float xk[4] = { kk == 0 ? xv[0].x : kk == 1 ? xv[0].y : kk == 2 ? xv[0].z : xv[0].w,
                            kk == 0 ? xv[1].x : kk == 1 ? xv[1].y : kk == 2 ? xv[1].z : xv[1].w,
                            kk == 0 ? xv[2].x : kk == 1 ? xv[2].y : kk == 2 ? xv[2].z : xv[2].w,
                            kk == 0 ? xv[3].x : kk == 1 ? xv[3].y : kk == 2 ? xv[3].z : xv[3].w };
#pragma unroll
            for (int r = 0; r < 4; r++) {
                float xs = xk[r];
                acc[r][0]  += xs * w0.x; acc[r][1]  += xs * w0.y;
                acc[r][2]  += xs * w0.z; acc[r][3]  += xs * w0.w;
                acc[r][4]  += xs * w1.x; acc[r][5]  += xs * w1.y;
                acc[r][6]  += xs * w1.z; acc[r][7]  += xs * w1.w;
                acc[r][8]  += xs * w2.x; acc[r][9]  += xs * w2.y;
                acc[r][10] += xs * w2.z; acc[r][11] += xs * w2.w;
                acc[r][12] += xs * w3.x; acc[r][13] += xs * w3.y;
                acc[r][14] += xs * w3.z; acc[r][15] += xs * w3.w;
            }
        }
    }

#pragma unroll
    for (int r = 0; r < 4; r++) {
        int row = row0 + r;
        float asum = 0.f, dsum = 0.f;
#pragma unroll
        for (int j = 0; j < 16; j++) {
            asum += acc[r][j] * as_s[jbase + j];
            dsum += acc[r][j] * ad_s[jbase + j];
        }
        // combine the 4 jq-slices (consecutive lanes of one warp)
        asum += __shfl_xor_sync(0xffffffff, asum, 1);
        asum += __shfl_xor_sync(0xffffffff, asum, 2);
        dsum += __shfl_xor_sync(0xffffffff, dsum, 1);
        dsum += __shfl_xor_sync(0xffffffff, dsum, 2);

        if (row < N_NODES) {
            float4* hp = (float4*)(g_h + (size_t)row * HID_C + jbase);
#pragma unroll
            for (int j4 = 0; j4 < 4; j4++)
                hp[j4] = make_float4(acc[r][4 * j4], acc[r][4 * j4 + 1],
                                     acc[r][4 * j4 + 2], acc[r][4 * j4 + 3]);
            if (jq == 0) {
                g_as[row] = asum;
                g_ad[row] = dsum;
                g_cnt[row] = 1;  // self-loop pre-counted; deterministic re-init on replay
            }
        }
    }
}

// ---------------- K2: in-degree count ----------------
__global__ void __launch_bounds__(256) k2_count(const int* __restrict__ ei) {
    int e = blockIdx.x * 256 + threadIdx.x;
    if (e >= N_EDGES) return;
    int is64 = g_is64;
    int d = load_idx(ei, N_EDGES + e, is64);
    atomicAdd(&g_cnt[d], 1);
}

// ---------------- K3a: per-block tile sums ----------------
__global__ void __launch_bounds__(SCAN_TILE) k3a_blocksum() {
    __shared__ int red[SCAN_TILE];
    int t = threadIdx.x;
    int idx = blockIdx.x * SCAN_TILE + t;
    red[t] = (idx < N_NODES) ? g_cnt[idx] : 0;
    __syncthreads();
#pragma unroll
    for (int s = SCAN_TILE / 2; s > 0; s >>= 1) {
        if (t < s) red[t] += red[t + s];
        __syncthreads();
    }
    if (t == 0) g_blksum[blockIdx.x] = red[0];
}

// ---------------- K3b: scan block sums ----------------
__global__ void __launch_bounds__(64) k3b_scanblk() {
    __shared__ int v[64];
    int t = threadIdx.x;
    v[t] = (t < NB_SCAN) ? g_blksum[t] : 0;
    __syncthreads();
#pragma unroll
    for (int off = 1; off < 64; off <<= 1) {
        int add = (t >= off) ? v[t - off] : 0;
        __syncthreads();
        v[t] += add;
        __syncthreads();
    }
    if (t < NB_SCAN) g_blkoff[t] = (t == 0) ? 0 : v[t - 1];
    if (t == 63) g_off[N_NODES] = v[63];
}

// ---------------- K3c: per-tile scan, emit offsets/self-loops/cursors --------
__global__ void __launch_bounds__(SCAN_TILE) k3c_emit() {
    __shared__ int v[SCAN_TILE];
    int t = threadIdx.x;
    int idx = blockIdx.x * SCAN_TILE + t;
    int c = (idx < N_NODES) ? g_cnt[idx] : 0;
    v[t] = c;
    __syncthreads();
#pragma unroll
    for (int off = 1; off < SCAN_TILE; off <<= 1) {
        int add = (t >= off) ? v[t - off] : 0;
        __syncthreads();
        v[t] += add;
        __syncthreads();
    }
    if (idx < N_NODES) {
        int o = g_blkoff[blockIdx.x] + v[t] - c;
        g_off[idx] = o;
        g_bucket[o] = idx;       // self-loop first in each segment
        g_cursor[idx] = o + 1;
    }
}

// ---------------- K4: CSR fill ----------------
__global__ void __launch_bounds__(256) k4_fill(const int* __restrict__ ei) {
    int e = blockIdx.x * 256 + threadIdx.x;
    if (e >= N_EDGES) return;
    int is64 = g_is64;
    int s = load_idx(ei, e, is64);
    int d = load_idx(ei, N_EDGES + e, is64);
    int pos = atomicAdd(&g_cursor[d], 1);
    g_bucket[pos] = s;
}

// ---------------- K5: gather + shift-free softmax + aggregate ----------------
__global__ void __launch_bounds__(256) k5_gather() {
    int gt = blockIdx.x * 256 + threadIdx.x;
    int d = gt >> 4;
    int lane = gt & 15;
    if (d >= N_NODES) return;

    float ad = g_ad[d];
    int beg = g_off[d];
    int end = g_off[d + 1];

    float4 acc = make_float4(0.f, 0.f, 0.f, 0.f);
    float sumex = 0.f;

    int s = g_bucket[beg];
    for (int e = beg; e < end; e++) {
        int s_next = (e + 1 < end) ? g_bucket[e + 1] : 0;
        float v = g_as[s] + ad;
        v = v > 0.f ? v : NEG_SLOPE * v;
        float ex = __expf(v);              // shift-free: logits bounded; softmax shift-invariant
        sumex += ex;
        float4 hv = *(const float4*)&g_h[(size_t)s * HID_C + lane * 4];
        acc.x += ex * hv.x; acc.y += ex * hv.y;
        acc.z += ex * hv.z; acc.w += ex * hv.w;
        s = s_next;
    }

    float inv = 1.f / (sumex + 1e-16f);
    *(float4*)&g_acc[(size_t)d * HID_C + lane * 4] =
        make_float4(acc.x * inv, acc.y * inv, acc.z * inv, acc.w * inv);
}

// ---------------- K6 v2: register-tiled  out = relu(acc+bc) @ W_lin + b_lin --
// 256 threads: jq = tid&3 (8-col slice), rslot = tid>>2 -> 4 rows each, 256 rows/block.
__global__ void __launch_bounds__(256) k6_out(const float* __restrict__ bias_conv,
                                              const float* __restrict__ W_lin,
                                              const float* __restrict__ b_lin,
                                              float* __restrict__ out) {
    __shared__ __align__(16) float Wl[HID_C * OUT_C];  // 8 KB, [c][j]
    __shared__ float bc[HID_C];
    __shared__ float bl[OUT_C];
    int tid = threadIdx.x;
    for (int i = tid; i < HID_C * OUT_C; i += 256) Wl[i] = W_lin[i];
    if (tid < HID_C) bc[tid] = bias_conv[tid];
    if (tid < OUT_C) bl[tid] = b_lin[tid];
    __syncthreads();

    const int jq = tid & 3;
    const int rslot = tid >> 2;
    const int jbase = jq * 8;
    const int row0 = blockIdx.x * 256 + rslot * 4;

    float acc[4][8];
#pragma unroll
    for (int r = 0; r < 4; r++)
#pragma unroll
        for (int j = 0; j < 8; j++) acc[r][j] = bl[jbase + j];

    const float4 z4 = make_float4(0.f, 0.f, 0.f, 0.f);
    for (int c4 = 0; c4 < HID_C / 4; c4++) {
        float4 av[4];
#pragma unroll
        for (int r = 0; r < 4; r++) {
            int row = row0 + r;
            av[r] = (row < N_NODES) ? *(const float4*)(g_acc + (size_t)row * HID_C + c4 * 4) : z4;
        }
        float4 bcv = *(const float4*)&bc[c4 * 4];
        float bca[4] = {bcv.x, bcv.y, bcv.z, bcv.w};
#pragma unroll
        for (int cc = 0; cc < 4; cc++) {
            int c = c4 * 4 + cc;
            const float4* wrow = (const float4*)&Wl[c * OUT_C + jbase];
            float4 w0 = wrow[0], w1 = wrow[1];
#pragma unroll
            for (int r = 0; r < 4; r++) {
                float v = (cc == 0 ? av[r].x : cc == 1 ? av[r].y : cc == 2 ? av[r].z : av[r].w) + bca[cc];
                v = v > 0.f ? v : 0.f;
                acc[r][0] += v * w0.x; acc[r][1] += v * w0.y;
                acc[r][2] += v * w0.z; acc[r][3] += v * w0.w;
                acc[r][4] += v * w1.x; acc[r][5] += v * w1.y;
                acc[r][6] += v * w1.z; acc[r][7] += v * w1.w;
            }
        }
    }

#pragma unroll
    for (int r = 0; r < 4; r++) {
        int row = row0 + r;
        if (row < N_NODES) {
            float4* op = (float4*)(out + (size_t)row * OUT_C + jbase);
            op[0] = make_float4(acc[r][0], acc[r][1], acc[r][2], acc[r][3]);
            op[1] = make_float4(acc[r][4], acc[r][5], acc[r][6], acc[r][7]);
        }
    }
}

// ---------------- launch ----------------
extern "C" void kernel_launch(void* const* d_in, const int* in_sizes, int n_in,
                              void* d_out, int out_size) {
    const float* x         = (const float*)d_in[0];
    const int*   ei        = (const int*)d_in[1];
    const float* W         = (const float*)d_in[2];
    const float* att_src   = (const float*)d_in[3];
    const float* att_dst   = (const float*)d_in[4];
    const float* bias_conv = (const float*)d_in[5];
    const float* W_lin     = (const float*)d_in[6];
    const float* b_lin     = (const float*)d_in[7];
    float* out             = (float*)d_out;

    (void)in_sizes; (void)n_in; (void)out_size;

    k0_detect<<<1, 256>>>(ei);
    k1_feat<<<(N_NODES + 255) / 256, 256>>>(x, W, att_src, att_dst);   // 256 rows/block
    k2_count<<<(N_EDGES + 255) / 256, 256>>>(ei);
    k3a_blocksum<<<NB_SCAN, SCAN_TILE>>>();
    k3b_scanblk<<<1, 64>>>();
    k3c_emit<<<NB_SCAN, SCAN_TILE>>>();
    k4_fill<<<(N_EDGES + 255) / 256, 256>>>(ei);
    {
        long long threads = (long long)N_NODES * 16;
        int blocks = (int)((threads + 255) / 256);
        k5_gather<<<blocks, 256>>>();
    }
    k6_out<<<(N_NODES + 255) / 256, 256>>>(bias_conv, W_lin, b_lin, out);
}